// round 2
// baseline (speedup 1.0000x reference)
#include <cuda_runtime.h>

#define KTOT   1000000
#define NCOLS  70400
#define SENT   -9999999.0f

typedef unsigned long long u64;

static __device__ __forceinline__ u64 pack2(float lo, float hi) {
    u64 r; asm("mov.b64 %0,{%1,%2};" : "=l"(r) : "f"(lo), "f"(hi)); return r;
}
static __device__ __forceinline__ void unpack2(u64 v, float& lo, float& hi) {
    asm("mov.b64 {%0,%1},%2;" : "=f"(lo), "=f"(hi) : "l"(v));
}
static __device__ __forceinline__ u64 fma2(u64 a, u64 b, u64 c) {
    u64 d; asm("fma.rn.f32x2 %0,%1,%2,%3;" : "=l"(d) : "l"(a), "l"(b), "l"(c)); return d;
}
static __device__ __forceinline__ u64 relu2(u64 v) {
    float lo, hi; unpack2(v, lo, hi);
    lo = fmaxf(lo, 0.0f); hi = fmaxf(hi, 0.0f);
    return pack2(lo, hi);
}
// float atomic max via sign-split integer atomics (no return needed -> REDG)
static __device__ __forceinline__ void atomicMaxF(float* a, float v) {
    if (v >= 0.0f) atomicMax((int*)a, __float_as_int(v));
    else           atomicMin((unsigned int*)a, __float_as_uint(v));
}

__global__ void init_out_kernel(float* out, int n) {
    int i = blockIdx.x * blockDim.x + threadIdx.x;
    if (i < n) out[i] = (i < NCOLS) ? SENT : 1.0f;   // trailing element(s) = flag
}

__global__ __launch_bounds__(256) void mlp_scatter_kernel(
    const float* __restrict__ x,        // (4, K) row-major
    const int* __restrict__ tix,        // (K, 2) int32, col index at [2k+1]
    const float* __restrict__ W1, const float* __restrict__ b1,
    const float* __restrict__ W2, const float* __restrict__ b2,
    const float* __restrict__ W3, const float* __restrict__ b3,
    const float* __restrict__ W4, const float* __restrict__ b4,
    float* __restrict__ out)
{
    // Weights duplicated into packed (w,w) 64-bit shared words: one LDS.64
    // broadcast feeds one FFMA2.
    __shared__ u64 sW1[72], sb1[18], sW2[648], sb2[36], sW3[1296], sb3[36], sW4[36], sb4;

    const int t = threadIdx.x;
    for (int i = t; i < 72;   i += 256) sW1[i] = pack2(W1[i], W1[i]);
    for (int i = t; i < 18;   i += 256) sb1[i] = pack2(b1[i], b1[i]);
    for (int i = t; i < 648;  i += 256) sW2[i] = pack2(W2[i], W2[i]);
    for (int i = t; i < 36;   i += 256) sb2[i] = pack2(b2[i], b2[i]);
    for (int i = t; i < 1296; i += 256) sW3[i] = pack2(W3[i], W3[i]);
    for (int i = t; i < 36;   i += 256) sb3[i] = pack2(b3[i], b3[i]);
    for (int i = t; i < 36;   i += 256) sW4[i] = pack2(W4[i], W4[i]);
    if (t == 0) sb4 = pack2(b4[0], b4[0]);
    __syncthreads();

    const long long k0 = 2LL * ((long long)blockIdx.x * 256 + t);
    if (k0 >= KTOT) return;

    // Two adjacent columns packed into f32x2 lanes.
    u64 xv[4];
    #pragma unroll
    for (int j = 0; j < 4; j++) {
        float2 v = *reinterpret_cast<const float2*>(x + (size_t)j * KTOT + k0);
        xv[j] = pack2(v.x, v.y);
    }

    // Layer 1: 4 -> 18  (fully unrolled, h1 register-resident)
    u64 h1[18];
    #pragma unroll
    for (int j = 0; j < 18; j++) {
        u64 a = sb1[j];
        #pragma unroll
        for (int i = 0; i < 4; i++) a = fma2(sW1[j * 4 + i], xv[i], a);
        h1[j] = relu2(a);
    }

    // Layer 2: 18 -> 36 (fully unrolled, h2 register-resident)
    u64 h2[36];
    #pragma unroll
    for (int j = 0; j < 36; j++) {
        u64 a = sb2[j];
        #pragma unroll
        for (int i = 0; i < 18; i++) a = fma2(sW2[j * 18 + i], h1[i], a);
        h2[j] = relu2(a);
    }

    // Layers 3+4 fused: 36 -> 36 -> 1. h3 never materialized.
    u64 vacc = sb4;
    #pragma unroll 6
    for (int j = 0; j < 36; j++) {
        u64 a = sb3[j];
        #pragma unroll
        for (int i = 0; i < 36; i++) a = fma2(sW3[j * 36 + i], h2[i], a);
        a = relu2(a);
        vacc = fma2(sW4[j], a, vacc);
    }

    float v0, v1; unpack2(vacc, v0, v1);

    const int c0 = tix[2 * (int)k0 + 1];
    const int c1 = tix[2 * (int)k0 + 3];
    if ((unsigned)c0 < NCOLS) atomicMaxF(out + c0, v0);
    if ((unsigned)c1 < NCOLS) atomicMaxF(out + c1, v1);
}

extern "C" void kernel_launch(void* const* d_in, const int* in_sizes, int n_in,
                              void* d_out, int out_size) {
    const float* x   = (const float*)d_in[0];
    const int*   tix = (const int*)d_in[1];
    const float* W1 = (const float*)d_in[2];
    const float* b1 = (const float*)d_in[3];
    const float* W2 = (const float*)d_in[4];
    const float* b2 = (const float*)d_in[5];
    const float* W3 = (const float*)d_in[6];
    const float* b3 = (const float*)d_in[7];
    const float* W4 = (const float*)d_in[8];
    const float* b4 = (const float*)d_in[9];
    float* out = (float*)d_out;

    init_out_kernel<<<(out_size + 255) / 256, 256>>>(out, out_size);

    const int nthreads = KTOT / 2;                 // 2 columns per thread
    mlp_scatter_kernel<<<(nthreads + 255) / 256, 256>>>(
        x, tix, W1, b1, W2, b2, W3, b3, W4, b4, out);
}

// round 3
// speedup vs baseline: 1.4243x; 1.4243x over previous
#include <cuda_runtime.h>

#define KTOT   1000000
#define NCOLS  70400
#define SENT   -9999999.0f

typedef unsigned long long u64;

static __device__ __forceinline__ u64 pack2(float lo, float hi) {
    u64 r; asm("mov.b64 %0,{%1,%2};" : "=l"(r) : "f"(lo), "f"(hi)); return r;
}
static __device__ __forceinline__ void unpack2(u64 v, float& lo, float& hi) {
    asm("mov.b64 {%0,%1},%2;" : "=f"(lo), "=f"(hi) : "l"(v));
}
static __device__ __forceinline__ u64 fma2(u64 a, u64 b, u64 c) {
    u64 d; asm("fma.rn.f32x2 %0,%1,%2,%3;" : "=l"(d) : "l"(a), "l"(b), "l"(c)); return d;
}
static __device__ __forceinline__ u64 relu2(u64 v) {
    float lo, hi; unpack2(v, lo, hi);
    lo = fmaxf(lo, 0.0f); hi = fmaxf(hi, 0.0f);
    return pack2(lo, hi);
}
// float atomic max via sign-split integer atomics (no return -> REDG)
static __device__ __forceinline__ void atomicMaxF(float* a, float v) {
    if (v >= 0.0f) atomicMax((int*)a, __float_as_int(v));
    else           atomicMin((unsigned int*)a, __float_as_uint(v));
}

__global__ void init_out_kernel(float* out, int n) {
    int i = blockIdx.x * blockDim.x + threadIdx.x;
    if (i < n) out[i] = (i < NCOLS) ? SENT : 1.0f;   // trailing element(s) = flag
}

__global__ __launch_bounds__(128) void mlp_scatter_kernel(
    const float* __restrict__ x,        // (4, K) row-major
    const int* __restrict__ tix,        // (K, 2) int32, col index at [2k+1]
    const float* __restrict__ W1, const float* __restrict__ b1,
    const float* __restrict__ W2, const float* __restrict__ b2,
    const float* __restrict__ W3, const float* __restrict__ b3,
    const float* __restrict__ W4, const float* __restrict__ b4,
    float* __restrict__ out)
{
    // Weights duplicated into packed (w,w) 64-bit shared words: one LDS.64
    // broadcast feeds TWO FFMA2s (one per column-pair).
    __shared__ u64 sW1[72], sb1[18], sW2[648], sb2[36], sW3[1296], sb3[36], sW4[36], sb4[1];

    const int t = threadIdx.x;
    for (int i = t; i < 72;   i += 128) sW1[i] = pack2(W1[i], W1[i]);
    for (int i = t; i < 18;   i += 128) sb1[i] = pack2(b1[i], b1[i]);
    for (int i = t; i < 648;  i += 128) sW2[i] = pack2(W2[i], W2[i]);
    for (int i = t; i < 36;   i += 128) sb2[i] = pack2(b2[i], b2[i]);
    for (int i = t; i < 1296; i += 128) sW3[i] = pack2(W3[i], W3[i]);
    for (int i = t; i < 36;   i += 128) sb3[i] = pack2(b3[i], b3[i]);
    for (int i = t; i < 36;   i += 128) sW4[i] = pack2(W4[i], W4[i]);
    if (t == 0) sb4[0] = pack2(b4[0], b4[0]);
    __syncthreads();

    const long long k0 = 4LL * ((long long)blockIdx.x * 128 + t);
    if (k0 >= KTOT) return;

    // Four adjacent columns: two f32x2 lanes (a = cols k0,k0+1; b = k0+2,k0+3)
    u64 xa[4], xb[4];
    #pragma unroll
    for (int j = 0; j < 4; j++) {
        float4 v = *reinterpret_cast<const float4*>(x + (size_t)j * KTOT + k0);
        xa[j] = pack2(v.x, v.y);
        xb[j] = pack2(v.z, v.w);
    }

    // Layer 1: 4 -> 18
    u64 h1a[18], h1b[18];
    #pragma unroll
    for (int j = 0; j < 18; j++) {
        u64 a = sb1[j], b = a;
        #pragma unroll
        for (int i = 0; i < 4; i++) {
            u64 w = sW1[j * 4 + i];
            a = fma2(w, xa[i], a);
            b = fma2(w, xb[i], b);
        }
        h1a[j] = relu2(a);
        h1b[j] = relu2(b);
    }

    // Layer 2: 18 -> 36
    u64 h2a[36], h2b[36];
    #pragma unroll 4
    for (int j = 0; j < 36; j++) {
        u64 a = sb2[j], b = a;
        #pragma unroll
        for (int i = 0; i < 18; i++) {
            u64 w = sW2[j * 18 + i];
            a = fma2(w, h1a[i], a);
            b = fma2(w, h1b[i], b);
        }
        h2a[j] = relu2(a);
        h2b[j] = relu2(b);
    }

    // Layers 3+4 fused: 36 -> 36 -> 1 (h3 never materialized)
    u64 va = sb4[0], vb = sb4[0];
    #pragma unroll 4
    for (int j = 0; j < 36; j++) {
        u64 a = sb3[j], b = a;
        #pragma unroll
        for (int i = 0; i < 36; i++) {
            u64 w = sW3[j * 36 + i];
            a = fma2(w, h2a[i], a);
            b = fma2(w, h2b[i], b);
        }
        a = relu2(a);
        b = relu2(b);
        u64 w4 = sW4[j];
        va = fma2(w4, a, va);
        vb = fma2(w4, b, vb);
    }

    float v0, v1, v2, v3;
    unpack2(va, v0, v1);
    unpack2(vb, v2, v3);

    // (K,2) int32 pairs: columns at odd positions
    const int4 p01 = *reinterpret_cast<const int4*>(tix + 2 * k0);
    const int4 p23 = *reinterpret_cast<const int4*>(tix + 2 * k0 + 4);
    if ((unsigned)p01.y < NCOLS) atomicMaxF(out + p01.y, v0);
    if ((unsigned)p01.w < NCOLS) atomicMaxF(out + p01.w, v1);
    if ((unsigned)p23.y < NCOLS) atomicMaxF(out + p23.y, v2);
    if ((unsigned)p23.w < NCOLS) atomicMaxF(out + p23.w, v3);
}

extern "C" void kernel_launch(void* const* d_in, const int* in_sizes, int n_in,
                              void* d_out, int out_size) {
    const float* x   = (const float*)d_in[0];
    const int*   tix = (const int*)d_in[1];
    const float* W1 = (const float*)d_in[2];
    const float* b1 = (const float*)d_in[3];
    const float* W2 = (const float*)d_in[4];
    const float* b2 = (const float*)d_in[5];
    const float* W3 = (const float*)d_in[6];
    const float* b3 = (const float*)d_in[7];
    const float* W4 = (const float*)d_in[8];
    const float* b4 = (const float*)d_in[9];
    float* out = (float*)d_out;

    init_out_kernel<<<(out_size + 255) / 256, 256>>>(out, out_size);

    const int nthreads = KTOT / 4;                 // 4 columns per thread
    mlp_scatter_kernel<<<(nthreads + 127) / 128, 128>>>(
        x, tix, W1, b1, W2, b2, W3, b3, W4, b4, out);
}

// round 4
// speedup vs baseline: 1.4928x; 1.0480x over previous
#include <cuda_runtime.h>

#define KTOT   1000000
#define NCOLS  70400
#define SENT   -9999999.0f

typedef unsigned long long u64;

static __device__ __forceinline__ u64 pack2(float lo, float hi) {
    u64 r; asm("mov.b64 %0,{%1,%2};" : "=l"(r) : "f"(lo), "f"(hi)); return r;
}
static __device__ __forceinline__ void unpack2(u64 v, float& lo, float& hi) {
    asm("mov.b64 {%0,%1},%2;" : "=f"(lo), "=f"(hi) : "l"(v));
}
static __device__ __forceinline__ u64 fma2(u64 a, u64 b, u64 c) {
    u64 d; asm("fma.rn.f32x2 %0,%1,%2,%3;" : "=l"(d) : "l"(a), "l"(b), "l"(c)); return d;
}
// horizontal add of the two f32 lanes (bias pre-folded into lane 0)
static __device__ __forceinline__ float hadd(u64 v) {
    float lo, hi; unpack2(v, lo, hi);
    return lo + hi;
}
// float atomic max via sign-split integer atomics (no return -> REDG)
static __device__ __forceinline__ void atomicMaxF(float* a, float v) {
    if (v >= 0.0f) atomicMax((int*)a, __float_as_int(v));
    else           atomicMin((unsigned int*)a, __float_as_uint(v));
}

__global__ void init_out_kernel(float* out, int n) {
    int i = blockIdx.x * blockDim.x + threadIdx.x;
    if (i < n) out[i] = (i < NCOLS) ? SENT : 1.0f;   // trailing element(s) = flag
}

__global__ __launch_bounds__(128) void mlp_scatter_kernel(
    const float* __restrict__ x,        // (4, K) row-major
    const int* __restrict__ tix,        // (K, 2) int32, col index at [2k+1]
    const float* __restrict__ W1, const float* __restrict__ b1,
    const float* __restrict__ W2, const float* __restrict__ b2,
    const float* __restrict__ W3, const float* __restrict__ b3,
    const float* __restrict__ W4, const float* __restrict__ b4,
    float* __restrict__ out)
{
    // k-packed weights: raw copies, each u64 = two consecutive weights of a row.
    // Rows: W1=4 floats (2 u64), W2=18 (9 u64), W3=36 (18 u64 = 9 u64x2), W4 flat.
    __shared__ u64 sW1[36], sb1[18], sW2[324], sb2[36], sb3[36], sW4[18];
    __shared__ ulonglong2 sW3[324];
    __shared__ float sb4s;

    const int t = threadIdx.x;
    for (int i = t; i < 36;  i += 128) sW1[i] = ((const u64*)W1)[i];
    for (int i = t; i < 18;  i += 128) sb1[i] = pack2(b1[i], 0.0f);
    for (int i = t; i < 324; i += 128) sW2[i] = ((const u64*)W2)[i];
    for (int i = t; i < 36;  i += 128) sb2[i] = pack2(b2[i], 0.0f);
    for (int i = t; i < 324; i += 128) sW3[i] = ((const ulonglong2*)W3)[i];
    for (int i = t; i < 36;  i += 128) sb3[i] = pack2(b3[i], 0.0f);
    for (int i = t; i < 18;  i += 128) sW4[i] = ((const u64*)W4)[i];
    if (t == 0) sb4s = b4[0];
    __syncthreads();

    const long long k0 = 4LL * ((long long)blockIdx.x * 128 + t);
    if (k0 >= KTOT) return;

    // Load 4 columns of the (4,K) input; repack per column along the i-dim.
    float4 r0 = *reinterpret_cast<const float4*>(x + 0 * (size_t)KTOT + k0);
    float4 r1 = *reinterpret_cast<const float4*>(x + 1 * (size_t)KTOT + k0);
    float4 r2 = *reinterpret_cast<const float4*>(x + 2 * (size_t)KTOT + k0);
    float4 r3 = *reinterpret_cast<const float4*>(x + 3 * (size_t)KTOT + k0);
    u64 xv[4][2];
    xv[0][0] = pack2(r0.x, r1.x); xv[0][1] = pack2(r2.x, r3.x);
    xv[1][0] = pack2(r0.y, r1.y); xv[1][1] = pack2(r2.y, r3.y);
    xv[2][0] = pack2(r0.z, r1.z); xv[2][1] = pack2(r2.z, r3.z);
    xv[3][0] = pack2(r0.w, r1.w); xv[3][1] = pack2(r2.w, r3.w);

    // ---- Layer 1: 4 -> 18, outputs packed in pairs: h1[c][j/2] ----
    u64 h1[4][9];
    #pragma unroll
    for (int j = 0; j < 18; j += 2) {
        float ho[2][4];
        #pragma unroll
        for (int s = 0; s < 2; s++) {
            const int jj = j + s;
            u64 w0 = sW1[jj * 2 + 0], w1 = sW1[jj * 2 + 1], bb = sb1[jj];
            #pragma unroll
            for (int c = 0; c < 4; c++) {
                u64 a = fma2(w0, xv[c][0], bb);
                a = fma2(w1, xv[c][1], a);
                ho[s][c] = fmaxf(hadd(a), 0.0f);
            }
        }
        #pragma unroll
        for (int c = 0; c < 4; c++) h1[c][j / 2] = pack2(ho[0][c], ho[1][c]);
    }

    // ---- Layer 2: 18 -> 36, outputs packed: h2[c][j/2] ----
    u64 h2[4][18];
    #pragma unroll
    for (int j = 0; j < 36; j += 2) {
        float ho[2][4];
        #pragma unroll
        for (int s = 0; s < 2; s++) {
            const int jj = j + s;
            u64 a0 = sb2[jj], a1 = sb2[jj], a2 = sb2[jj], a3 = sb2[jj];
            #pragma unroll
            for (int i = 0; i < 9; i++) {
                u64 w = sW2[jj * 9 + i];
                a0 = fma2(w, h1[0][i], a0);
                a1 = fma2(w, h1[1][i], a1);
                a2 = fma2(w, h1[2][i], a2);
                a3 = fma2(w, h1[3][i], a3);
            }
            ho[s][0] = fmaxf(hadd(a0), 0.0f);
            ho[s][1] = fmaxf(hadd(a1), 0.0f);
            ho[s][2] = fmaxf(hadd(a2), 0.0f);
            ho[s][3] = fmaxf(hadd(a3), 0.0f);
        }
        #pragma unroll
        for (int c = 0; c < 4; c++) h2[c][j / 2] = pack2(ho[0][c], ho[1][c]);
    }

    // ---- Layers 3+4 fused: 36 -> 36 -> 1 (h3 never stored) ----
    u64 vacc[4];
    #pragma unroll
    for (int c = 0; c < 4; c++) vacc[c] = pack2(sb4s, 0.0f);

    for (int j = 0; j < 36; j += 2) {
        float ho[2][4];
        #pragma unroll
        for (int s = 0; s < 2; s++) {
            const int jj = j + s;
            u64 a0 = sb3[jj], a1 = sb3[jj], a2 = sb3[jj], a3 = sb3[jj];
            #pragma unroll
            for (int q = 0; q < 9; q++) {
                ulonglong2 w = sW3[jj * 9 + q];
                a0 = fma2(w.x, h2[0][2 * q], a0);
                a1 = fma2(w.x, h2[1][2 * q], a1);
                a2 = fma2(w.x, h2[2][2 * q], a2);
                a3 = fma2(w.x, h2[3][2 * q], a3);
                a0 = fma2(w.y, h2[0][2 * q + 1], a0);
                a1 = fma2(w.y, h2[1][2 * q + 1], a1);
                a2 = fma2(w.y, h2[2][2 * q + 1], a2);
                a3 = fma2(w.y, h2[3][2 * q + 1], a3);
            }
            ho[s][0] = fmaxf(hadd(a0), 0.0f);
            ho[s][1] = fmaxf(hadd(a1), 0.0f);
            ho[s][2] = fmaxf(hadd(a2), 0.0f);
            ho[s][3] = fmaxf(hadd(a3), 0.0f);
        }
        u64 w4 = sW4[j / 2];
        #pragma unroll
        for (int c = 0; c < 4; c++)
            vacc[c] = fma2(w4, pack2(ho[0][c], ho[1][c]), vacc[c]);
    }

    float v0 = hadd(vacc[0]), v1 = hadd(vacc[1]);
    float v2 = hadd(vacc[2]), v3 = hadd(vacc[3]);

    // (K,2) int32 pairs: column index at odd positions
    const int4 p01 = *reinterpret_cast<const int4*>(tix + 2 * k0);
    const int4 p23 = *reinterpret_cast<const int4*>(tix + 2 * k0 + 4);
    if ((unsigned)p01.y < NCOLS) atomicMaxF(out + p01.y, v0);
    if ((unsigned)p01.w < NCOLS) atomicMaxF(out + p01.w, v1);
    if ((unsigned)p23.y < NCOLS) atomicMaxF(out + p23.y, v2);
    if ((unsigned)p23.w < NCOLS) atomicMaxF(out + p23.w, v3);
}

extern "C" void kernel_launch(void* const* d_in, const int* in_sizes, int n_in,
                              void* d_out, int out_size) {
    const float* x   = (const float*)d_in[0];
    const int*   tix = (const int*)d_in[1];
    const float* W1 = (const float*)d_in[2];
    const float* b1 = (const float*)d_in[3];
    const float* W2 = (const float*)d_in[4];
    const float* b2 = (const float*)d_in[5];
    const float* W3 = (const float*)d_in[6];
    const float* b3 = (const float*)d_in[7];
    const float* W4 = (const float*)d_in[8];
    const float* b4 = (const float*)d_in[9];
    float* out = (float*)d_out;

    init_out_kernel<<<(out_size + 255) / 256, 256>>>(out, out_size);

    const int nthreads = KTOT / 4;                 // 4 columns per thread
    mlp_scatter_kernel<<<(nthreads + 127) / 128, 128>>>(
        x, tix, W1, b1, W2, b2, W3, b3, W4, b4, out);
}